// round 12
// baseline (speedup 1.0000x reference)
#include <cuda_runtime.h>
#include <cuda_fp16.h>
#include <cstdint>

// IndRNN (sm_103a, baseline-PTX -> warp mma.sync):
//   proj = x @ W + b : single-pass FP16 HMMA GEMM (m16n8k16, fp32 accum).
//     fp16 mantissa == tf32 mantissa (10 bits) -> same rel_err as tf32 pass,
//     at 2x MACs/instruction. A: LDG fp32 -> cvt -> STS. B: fp16 W^T prepass.
//   scan: h_t = relu(proj_t + h_{t-1}*clip(u,0,1)); round-9 scalar pipelined
//         (at 6.3 TB/s combined LTS/HBM roofline; done).

#define M_DIM 32768
#define K_DIM 256
#define U_DIM 512

// W^T fp16 scratch [N,K] (0.25 MB)
__device__ __align__(16) __half g_wt[U_DIM * K_DIM];

// ---------------------------------------------------------------------------
__device__ __forceinline__ uint32_t smem_u32(const void* p) {
    uint32_t a;
    asm("{ .reg .u64 t; cvta.to.shared.u64 t, %1; cvt.u32.u64 %0, t; }" : "=r"(a) : "l"(p));
    return a;
}
__device__ __forceinline__ void cp_async16(uint32_t saddr, const void* gptr) {
    asm volatile("cp.async.cg.shared.global [%0], [%1], 16;" :: "r"(saddr), "l"(gptr));
}
__device__ __forceinline__ void cp_commit() { asm volatile("cp.async.commit_group;"); }
__device__ __forceinline__ void cp_wait0() { asm volatile("cp.async.wait_group 0;"); }

__device__ __forceinline__ void mma16816_f16(float* c, const uint32_t* a,
                                             uint32_t b0, uint32_t b1) {
    asm volatile(
        "mma.sync.aligned.m16n8k16.row.col.f32.f16.f16.f32 "
        "{%0,%1,%2,%3}, {%4,%5,%6,%7}, {%8,%9}, {%0,%1,%2,%3};"
        : "+f"(c[0]), "+f"(c[1]), "+f"(c[2]), "+f"(c[3])
        : "r"(a[0]), "r"(a[1]), "r"(a[2]), "r"(a[3]), "r"(b0), "r"(b1));
}
__device__ __forceinline__ uint32_t pack_h2(float x, float y) {
    __half2 h = __floats2half2_rn(x, y);
    return *(uint32_t*)&h;
}

// ---------------------------------------------------------------------------
// W transpose -> fp16 (once per launch)
// ---------------------------------------------------------------------------
__global__ void wsplit_kernel(const float* __restrict__ W) {
    __shared__ float tile[32][33];
    int k0 = blockIdx.y * 32, u0 = blockIdx.x * 32;
    int tx = threadIdx.x, ty = threadIdx.y;  // 32 x 8
#pragma unroll
    for (int i = 0; i < 32; i += 8)
        tile[ty + i][tx] = W[(size_t)(k0 + ty + i) * U_DIM + u0 + tx];
    __syncthreads();
#pragma unroll
    for (int i = 0; i < 32; i += 8)
        g_wt[(size_t)(u0 + ty + i) * K_DIM + k0 + tx] = __float2half_rn(tile[tx][ty + i]);
}

// ---------------------------------------------------------------------------
// FP16 HMMA GEMM: CTA 128(M)x128(N), BK=32, 8 warps (4M x 2N), warp 32x64.
// Smem: A part + B part, each 128 rows x 32 fp16, pitch 80B (proven conflict-
// free in round 4). Double-buffered. A one stage ahead via LDG->cvt->STS.
// ---------------------------------------------------------------------------
#define APITCH 80
#define PART_BYTES (128 * APITCH)          // 10240
#define STAGE_BYTES (2 * PART_BYTES)       // 20480
#define GEMM_SMEM (2 * STAGE_BYTES)        // 40960

__global__ __launch_bounds__(256) void indrnn_gemm_f16(
    const float* __restrict__ X, const float* __restrict__ bias, float* __restrict__ C)
{
    extern __shared__ __align__(16) char smem[];
    const uint32_t sbase = smem_u32(smem);

    const int tid = threadIdx.x;
    const int lane = tid & 31, warp = tid >> 5;
    const int wm = (warp & 3) * 32;
    const int wn = (warp >> 2) * 64;
    const int g = lane >> 2, tig = lane & 3;

    const int n0 = blockIdx.x * 128;
    const int m0 = blockIdx.y * 128;

    // A geometry: 1024 float4 chunks/stage (128 rows x 8 float4), 4 per thread
    int ar[4], ac4[4];
#pragma unroll
    for (int j = 0; j < 4; j++) {
        int q = tid + j * 256;
        ar[j] = q >> 3;
        ac4[j] = q & 7;
    }

    auto ldgA = [&](int k0, float4* regs) {
#pragma unroll
        for (int j = 0; j < 4; j++)
            regs[j] = *(const float4*)&X[(size_t)(m0 + ar[j]) * K_DIM + k0 + ac4[j] * 4];
    };
    auto stsA = [&](int buf, const float4* regs) {
        char* s0 = smem + buf * STAGE_BYTES;
#pragma unroll
        for (int j = 0; j < 4; j++) {
            uint2 t;
            t.x = pack_h2(regs[j].x, regs[j].y);
            t.y = pack_h2(regs[j].z, regs[j].w);
            *(uint2*)(s0 + ar[j] * APITCH + ac4[j] * 8) = t;
        }
    };
    // B: 512 x 16B chunks (128 rows x 4 units of 8 fp16), 2 per thread
    auto cpB = [&](int buf, int k0) {
        const uint32_t s0 = sbase + buf * STAGE_BYTES + PART_BYTES;
#pragma unroll
        for (int j = 0; j < 2; j++) {
            int c = tid + j * 256;       // 0..511
            int r = c >> 2, unit = c & 3;
            cp_async16(s0 + r * APITCH + unit * 16,
                       g_wt + (size_t)(n0 + r) * K_DIM + k0 + unit * 8);
        }
    };

    float acc[2][8][4];
#pragma unroll
    for (int ms = 0; ms < 2; ms++)
#pragma unroll
        for (int ns = 0; ns < 8; ns++)
#pragma unroll
            for (int i = 0; i < 4; i++) acc[ms][ns][i] = 0.0f;

    const int NKT = K_DIM / 32;  // 8
    float4 regs[4];

    // Prologue
    ldgA(0, regs);
    cpB(0, 0);
    cp_commit();
    stsA(0, regs);
    ldgA(32, regs);
    cp_wait0();
    __syncthreads();

    for (int kt = 0; kt < NKT; kt++) {
        const int buf = kt & 1;

        if (kt + 1 < NKT) {
            stsA(buf ^ 1, regs);
            cpB(buf ^ 1, (kt + 1) * 32);
            cp_commit();
        }
        if (kt + 2 < NKT) ldgA((kt + 2) * 32, regs);

        const char* sA = smem + buf * STAGE_BYTES;
        const char* sB = sA + PART_BYTES;

#pragma unroll
        for (int ks = 0; ks < 2; ks++) {
            const int cb = ks * 32 + tig * 4;   // k16 step: 32B; frag col: tig*4
            uint32_t a[2][4];
#pragma unroll
            for (int ms = 0; ms < 2; ms++) {
                const int r = wm + ms * 16 + g;
                a[ms][0] = *(const uint32_t*)(sA + r * APITCH + cb);
                a[ms][1] = *(const uint32_t*)(sA + (r + 8) * APITCH + cb);
                a[ms][2] = *(const uint32_t*)(sA + r * APITCH + cb + 16);
                a[ms][3] = *(const uint32_t*)(sA + (r + 8) * APITCH + cb + 16);
            }
#pragma unroll
            for (int ns = 0; ns < 8; ns++) {
                const int br = wn + ns * 8 + g;
                uint32_t b0 = *(const uint32_t*)(sB + br * APITCH + cb);
                uint32_t b1 = *(const uint32_t*)(sB + br * APITCH + cb + 16);
#pragma unroll
                for (int ms = 0; ms < 2; ms++)
                    mma16816_f16(acc[ms][ns], a[ms], b0, b1);
            }
        }
        if (kt + 1 < NKT) cp_wait0();
        __syncthreads();
    }

    // Epilogue: +bias, f32 pair stores
#pragma unroll
    for (int ns = 0; ns < 8; ns++) {
        const int n = n0 + wn + ns * 8 + 2 * tig;
        float2 bb = *(const float2*)(bias + n);
#pragma unroll
        for (int ms = 0; ms < 2; ms++) {
            const int m = m0 + wm + ms * 16 + g;
            float2 o0, o1;
            o0.x = acc[ms][ns][0] + bb.x;
            o0.y = acc[ms][ns][1] + bb.y;
            o1.x = acc[ms][ns][2] + bb.x;
            o1.y = acc[ms][ns][3] + bb.y;
            *(float2*)(C + (size_t)m * U_DIM + n) = o0;
            *(float2*)(C + (size_t)(m + 8) * U_DIM + n) = o1;
        }
    }
}

// ---------------------------------------------------------------------------
__global__ void indrnn_gemm_naive(
    const float* __restrict__ A, const float* __restrict__ Bw,
    const float* __restrict__ bias, float* __restrict__ Cc,
    int M, int N, int K)
{
    int idx = blockIdx.x * blockDim.x + threadIdx.x;
    if (idx >= M * N) return;
    int m = idx / N, n = idx % N;
    float s = bias[n];
    for (int k = 0; k < K; k++) s = fmaf(A[(size_t)m * K + k], Bw[(size_t)k * N + n], s);
    Cc[idx] = s;
}

// ---------------------------------------------------------------------------
// Scan (round-9 proven): one thread per (b,u) chain; depth-32 software
// pipeline. Runs at the 6.3 TB/s combined LTS/HBM roofline.
// ---------------------------------------------------------------------------
__global__ __launch_bounds__(128) void indrnn_scan(
    float* __restrict__ out, const float* __restrict__ h0,
    const float* __restrict__ u, int B, int T, int U)
{
    int idx = blockIdx.x * blockDim.x + threadIdx.x;
    if (idx >= B * U) return;
    int b = idx / U;
    int j = idx - b * U;

    float uc = fminf(fmaxf(u[j], 0.0f), 1.0f);
    float h = h0[idx];
    const size_t st = (size_t)U;
    float* p = out + (size_t)b * T * U + j;

    if ((T & 31) == 0 && T >= 64) {
        float cur[32], nxt[32];
#pragma unroll
        for (int i = 0; i < 32; i++) cur[i] = __ldcg(p + i * st);
        float* pw = p;
        p += 32 * st;

        const int NB = T / 32;
        for (int bI = 1; bI < NB; bI++) {
#pragma unroll
            for (int i = 0; i < 32; i++) nxt[i] = __ldcg(p + i * st);
#pragma unroll
            for (int i = 0; i < 32; i++) {
                h = fmaxf(fmaf(h, uc, cur[i]), 0.0f);
                pw[i * st] = h;
            }
#pragma unroll
            for (int i = 0; i < 32; i++) cur[i] = nxt[i];
            pw = p;
            p += 32 * st;
        }
#pragma unroll
        for (int i = 0; i < 32; i++) {
            h = fmaxf(fmaf(h, uc, cur[i]), 0.0f);
            pw[i * st] = h;
        }
    } else {
        for (int t = 0; t < T; t++) {
            float v = __ldcg(p);
            h = fmaxf(fmaf(h, uc, v), 0.0f);
            *p = h;
            p += st;
        }
    }
}

// ---------------------------------------------------------------------------
extern "C" void kernel_launch(void* const* d_in, const int* in_sizes, int n_in,
                              void* d_out, int out_size)
{
    const float* x  = (const float*)d_in[0];
    const float* h0 = (const float*)d_in[1];
    const float* W  = (const float*)d_in[2];
    const float* u  = (const float*)d_in[3];
    const float* bb = (const float*)d_in[4];
    float* out = (float*)d_out;

    const int U = in_sizes[3];
    const int B = in_sizes[1] / U;
    const int D = in_sizes[2] / U;
    const int T = in_sizes[0] / (B * D);

    const int M = B * T;
    const int N = U;
    const int K = D;

    if (M == M_DIM && N == U_DIM && K == K_DIM) {
        wsplit_kernel<<<dim3(U_DIM / 32, K_DIM / 32), dim3(32, 8)>>>(W);
        cudaFuncSetAttribute(indrnn_gemm_f16,
                             cudaFuncAttributeMaxDynamicSharedMemorySize, GEMM_SMEM);
        indrnn_gemm_f16<<<dim3(N / 128, M / 128), 256, GEMM_SMEM>>>(x, bb, out);
    } else {
        int total = M * N;
        indrnn_gemm_naive<<<(total + 255) / 256, 256>>>(x, W, bb, out, M, N, K);
    }

    int chains = B * U;
    indrnn_scan<<<(chains + 127) / 128, 128>>>(out, h0, u, B, T, U);
}

// round 13
// speedup vs baseline: 1.1143x; 1.1143x over previous
#include <cuda_runtime.h>
#include <cuda_fp16.h>
#include <cstdint>

// IndRNN (sm_103a, baseline-PTX -> warp mma.sync tf32):
//   proj = x @ W + b : single-pass TF32 HMMA GEMM (at mma.sync MAC ceiling,
//                      ~256 MAC/cyc/SM — format-independent, measured R4/R5/R12).
//   Handoff: proj stored as fp16 scratch (33.5 MB, L2-resident) — halves the
//   GEMM->scan traffic. Scan reads fp16, writes fp32 out.

#define M_DIM 32768
#define K_DIM 256
#define U_DIM 512

// fp16 proj scratch [M, U] (33.5 MB static; allowed scratch form)
__device__ __align__(16) __half g_proj[(size_t)M_DIM * U_DIM];

// ---------------------------------------------------------------------------
__device__ __forceinline__ uint32_t smem_u32(const void* p) {
    uint32_t a;
    asm("{ .reg .u64 t; cvta.to.shared.u64 t, %1; cvt.u32.u64 %0, t; }" : "=r"(a) : "l"(p));
    return a;
}
__device__ __forceinline__ void cp_async16(uint32_t saddr, const void* gptr) {
    asm volatile("cp.async.cg.shared.global [%0], [%1], 16;" :: "r"(saddr), "l"(gptr));
}
__device__ __forceinline__ void cp_commit() { asm volatile("cp.async.commit_group;"); }
__device__ __forceinline__ void cp_wait0() { asm volatile("cp.async.wait_group 0;"); }

__device__ __forceinline__ uint32_t f2tf32(float f) {
    uint32_t r;
    asm("cvt.rna.tf32.f32 %0, %1;" : "=r"(r) : "f"(f));
    return r;
}
__device__ __forceinline__ void mma16888(float* c, const uint32_t* a, uint32_t b0, uint32_t b1) {
    asm volatile(
        "mma.sync.aligned.m16n8k8.row.col.f32.tf32.tf32.f32 "
        "{%0,%1,%2,%3}, {%4,%5,%6,%7}, {%8,%9}, {%0,%1,%2,%3};"
        : "+f"(c[0]), "+f"(c[1]), "+f"(c[2]), "+f"(c[3])
        : "r"(a[0]), "r"(a[1]), "r"(a[2]), "r"(a[3]), "r"(b0), "r"(b1));
}

// ---------------------------------------------------------------------------
// TF32 HMMA GEMM (R9 proven): CTA 128x128, BK=32, 8 warps (4M x 2N).
// A smem pitch 144B; B smem native [k][n] pitch 544B (conflict-free).
// Epilogue: +bias, convert to fp16, store to g_proj (half the write bytes).
// ---------------------------------------------------------------------------
#define APITCH 144
#define BPITCH 544
#define PART_A (128 * APITCH)
#define PART_B (32 * BPITCH)
#define STAGE_BYTES (PART_A + PART_B)
#define GEMM_SMEM (2 * STAGE_BYTES)

__global__ __launch_bounds__(256) void indrnn_gemm_tf32(
    const float* __restrict__ X, const float* __restrict__ W,
    const float* __restrict__ bias)
{
    extern __shared__ __align__(16) char smem[];
    const uint32_t sbase = smem_u32(smem);

    const int tid = threadIdx.x;
    const int lane = tid & 31, warp = tid >> 5;
    const int wm = (warp & 3) * 32;
    const int wn = (warp >> 2) * 64;
    const int g = lane >> 2, tig = lane & 3;

    const int n0 = blockIdx.x * 128;
    const int m0 = blockIdx.y * 128;

    int ar[4], ac4[4];
#pragma unroll
    for (int j = 0; j < 4; j++) {
        int q = tid + j * 256;
        ar[j] = q >> 3;
        ac4[j] = q & 7;
    }

    auto ldgA = [&](int k0, float4* regs) {
#pragma unroll
        for (int j = 0; j < 4; j++)
            regs[j] = *(const float4*)&X[(size_t)(m0 + ar[j]) * K_DIM + k0 + ac4[j] * 4];
    };
    auto stsA = [&](int buf, const float4* regs) {
        char* s0 = smem + buf * STAGE_BYTES;
#pragma unroll
        for (int j = 0; j < 4; j++) {
            uint4 t;
            t.x = f2tf32(regs[j].x);
            t.y = f2tf32(regs[j].y);
            t.z = f2tf32(regs[j].z);
            t.w = f2tf32(regs[j].w);
            *(uint4*)(s0 + ar[j] * APITCH + ac4[j] * 16) = t;
        }
    };
    auto cpB = [&](int buf, int k0) {
        const uint32_t s0 = sbase + buf * STAGE_BYTES + PART_A;
#pragma unroll
        for (int j = 0; j < 4; j++) {
            int c = tid + j * 256;
            int r = c >> 5, unit = c & 31;
            cp_async16(s0 + r * BPITCH + unit * 16,
                       W + (size_t)(k0 + r) * U_DIM + n0 + unit * 4);
        }
    };

    float acc[2][8][4];
#pragma unroll
    for (int ms = 0; ms < 2; ms++)
#pragma unroll
        for (int ns = 0; ns < 8; ns++)
#pragma unroll
            for (int i = 0; i < 4; i++) acc[ms][ns][i] = 0.0f;

    const int NKT = K_DIM / 32;  // 8
    float4 regs[4];

    ldgA(0, regs);
    cpB(0, 0);
    cp_commit();
    stsA(0, regs);
    ldgA(32, regs);
    cp_wait0();
    __syncthreads();

    for (int kt = 0; kt < NKT; kt++) {
        const int buf = kt & 1;

        if (kt + 1 < NKT) {
            stsA(buf ^ 1, regs);
            cpB(buf ^ 1, (kt + 1) * 32);
            cp_commit();
        }
        if (kt + 2 < NKT) ldgA((kt + 2) * 32, regs);

        const char* sA = smem + buf * STAGE_BYTES;
        const char* sB = sA + PART_A;

#pragma unroll
        for (int ks = 0; ks < 4; ks++) {
            const int cb = ks * 32 + tig * 4;
            uint32_t a[2][4];
#pragma unroll
            for (int ms = 0; ms < 2; ms++) {
                const int r = wm + ms * 16 + g;
                a[ms][0] = *(const uint32_t*)(sA + r * APITCH + cb);
                a[ms][1] = *(const uint32_t*)(sA + (r + 8) * APITCH + cb);
                a[ms][2] = *(const uint32_t*)(sA + r * APITCH + cb + 16);
                a[ms][3] = *(const uint32_t*)(sA + (r + 8) * APITCH + cb + 16);
            }
            const char* bn = sB + (ks * 8 + tig) * BPITCH + (wn + g) * 4;
#pragma unroll
            for (int ns = 0; ns < 8; ns++) {
                uint32_t b0 = f2tf32(*(const float*)(bn + ns * 32));
                uint32_t b1 = f2tf32(*(const float*)(bn + 4 * BPITCH + ns * 32));
#pragma unroll
                for (int ms = 0; ms < 2; ms++)
                    mma16888(acc[ms][ns], a[ms], b0, b1);
            }
        }
        if (kt + 1 < NKT) cp_wait0();
        __syncthreads();
    }

    // Epilogue: +bias, convert to fp16, store half2 pairs to g_proj
#pragma unroll
    for (int ns = 0; ns < 8; ns++) {
        const int n = n0 + wn + ns * 8 + 2 * tig;
        float2 bb = *(const float2*)(bias + n);
#pragma unroll
        for (int ms = 0; ms < 2; ms++) {
            const int m = m0 + wm + ms * 16 + g;
            __half2 h0p = __floats2half2_rn(acc[ms][ns][0] + bb.x, acc[ms][ns][1] + bb.y);
            __half2 h1p = __floats2half2_rn(acc[ms][ns][2] + bb.x, acc[ms][ns][3] + bb.y);
            *(__half2*)(g_proj + (size_t)m * U_DIM + n) = h0p;
            *(__half2*)(g_proj + (size_t)(m + 8) * U_DIM + n) = h1p;
        }
    }
}

// ---------------------------------------------------------------------------
// Fallback SIMT GEMM (writes fp32 out directly) for unexpected shapes.
// ---------------------------------------------------------------------------
__global__ void indrnn_gemm_naive(
    const float* __restrict__ A, const float* __restrict__ Bw,
    const float* __restrict__ bias, float* __restrict__ Cc,
    int M, int N, int K)
{
    int idx = blockIdx.x * blockDim.x + threadIdx.x;
    if (idx >= M * N) return;
    int m = idx / N, n = idx % N;
    float s = bias[n];
    for (int k = 0; k < K; k++) s = fmaf(A[(size_t)m * K + k], Bw[(size_t)k * N + n], s);
    Cc[idx] = s;
}

// ---------------------------------------------------------------------------
// Scan (fast path): reads fp16 g_proj (L2-resident), writes fp32 out.
// One thread per (b,u) chain; depth-32 software-pipelined (R9 structure).
// ---------------------------------------------------------------------------
__global__ __launch_bounds__(128) void indrnn_scan_h(
    float* __restrict__ out, const float* __restrict__ h0,
    const float* __restrict__ u, int B, int T, int U)
{
    int idx = blockIdx.x * blockDim.x + threadIdx.x;
    if (idx >= B * U) return;
    int b = idx / U;
    int j = idx - b * U;

    float uc = fminf(fmaxf(u[j], 0.0f), 1.0f);
    float h = h0[idx];
    const size_t st = (size_t)U;
    const __half* p = g_proj + (size_t)b * T * U + j;
    float* q = out + (size_t)b * T * U + j;

    if ((T & 31) == 0 && T >= 64) {
        float cur[32], nxt[32];
#pragma unroll
        for (int i = 0; i < 32; i++) cur[i] = __half2float(__ldcg(p + i * st));
        p += 32 * st;

        const int NB = T / 32;
        for (int bI = 1; bI < NB; bI++) {
#pragma unroll
            for (int i = 0; i < 32; i++) nxt[i] = __half2float(__ldcg(p + i * st));
#pragma unroll
            for (int i = 0; i < 32; i++) {
                h = fmaxf(fmaf(h, uc, cur[i]), 0.0f);
                q[i * st] = h;
            }
#pragma unroll
            for (int i = 0; i < 32; i++) cur[i] = nxt[i];
            q += 32 * st;
            p += 32 * st;
        }
#pragma unroll
        for (int i = 0; i < 32; i++) {
            h = fmaxf(fmaf(h, uc, cur[i]), 0.0f);
            q[i * st] = h;
        }
    } else {
        for (int t = 0; t < T; t++) {
            h = fmaxf(fmaf(h, uc, __half2float(__ldcg(p))), 0.0f);
            *q = h;
            p += st;
            q += st;
        }
    }
}

// Fallback scan: reads fp32 proj already in out, rewrites in place.
__global__ __launch_bounds__(128) void indrnn_scan1(
    float* __restrict__ out, const float* __restrict__ h0,
    const float* __restrict__ u, int B, int T, int U)
{
    int idx = blockIdx.x * blockDim.x + threadIdx.x;
    if (idx >= B * U) return;
    int b = idx / U;
    int j = idx - b * U;
    float uc = fminf(fmaxf(u[j], 0.0f), 1.0f);
    float h = h0[idx];
    float* p = out + (size_t)b * T * U + j;
    for (int t = 0; t < T; t++) {
        float v = __ldcg(p);
        h = fmaxf(fmaf(h, uc, v), 0.0f);
        *p = h;
        p += (size_t)U;
    }
}

// ---------------------------------------------------------------------------
extern "C" void kernel_launch(void* const* d_in, const int* in_sizes, int n_in,
                              void* d_out, int out_size)
{
    const float* x  = (const float*)d_in[0];
    const float* h0 = (const float*)d_in[1];
    const float* W  = (const float*)d_in[2];
    const float* u  = (const float*)d_in[3];
    const float* bb = (const float*)d_in[4];
    float* out = (float*)d_out;

    const int U = in_sizes[3];
    const int B = in_sizes[1] / U;
    const int D = in_sizes[2] / U;
    const int T = in_sizes[0] / (B * D);

    const int M = B * T;
    const int N = U;
    const int K = D;

    if (M == M_DIM && N == U_DIM && K == K_DIM) {
        cudaFuncSetAttribute(indrnn_gemm_tf32,
                             cudaFuncAttributeMaxDynamicSharedMemorySize, GEMM_SMEM);
        indrnn_gemm_tf32<<<dim3(N / 128, M / 128), 256, GEMM_SMEM>>>(x, W, bb);
        int chains = B * U;
        indrnn_scan_h<<<(chains + 127) / 128, 128>>>(out, h0, u, B, T, U);
    } else {
        int total = M * N;
        indrnn_gemm_naive<<<(total + 255) / 256, 256>>>(x, W, bb, out, M, N, K);
        int chains = B * U;
        indrnn_scan1<<<(chains + 127) / 128, 128>>>(out, h0, u, B, T, U);
    }
}